// round 11
// baseline (speedup 1.0000x reference)
#include <cuda_runtime.h>
#include <cuda_fp16.h>
#include <cstdint>
#include <cstddef>

#define NB 8
#define NN 2048
#define FD 128

// ---------------- device scratch (no cudaMalloc allowed) ----------------
__device__ float g_dis[NB * NN];
__device__ __half g_Ah[(size_t)NB * NN * NN];   // fp16(dis[n]*adj[n,m])
__device__ __half g_HhA[NB * FD * NN];          // H transposed [b][f][m], buffer A
__device__ __half g_HhB[NB * FD * NN];          // buffer B
__device__ __half g_Xh1[NB * NN * FD];          // fp16 X1 (for residual)
__device__ float g_Wr[3 * FD * FD];             // tf32 weights (layer-0 small GEMM)
__device__ __half g_Wh[2][FD * FD];             // fp16 W^T for W2, W3: [fo][fi]

// ---------------- helpers ----------------
__device__ __forceinline__ uint32_t cvt_rna(float x) {
    uint32_t r;
    asm("cvt.rna.tf32.f32 %0, %1;" : "=r"(r) : "f"(x));
    return r;
}
__device__ __forceinline__ void cp16(uint32_t smem_dst, const void* gsrc) {
    asm volatile("cp.async.cg.shared.global [%0], [%1], 16;" :: "r"(smem_dst), "l"(gsrc));
}
#define SWZ128(o) ((o) ^ (((o) >> 3) & 0x70))

#define LDSM4(R, a) \
    asm volatile("ldmatrix.sync.aligned.m8n8.x4.shared.b16 {%0,%1,%2,%3}, [%4];" \
        : "=r"((R)[0]), "=r"((R)[1]), "=r"((R)[2]), "=r"((R)[3]) : "r"(a))

__device__ __forceinline__ void mma_f16(float* c, const uint32_t* a, const uint32_t* b) {
    asm volatile(
        "mma.sync.aligned.m16n8k16.row.col.f32.f16.f16.f32 "
        "{%0,%1,%2,%3}, {%4,%5,%6,%7}, {%8,%9}, {%0,%1,%2,%3};"
        : "+f"(c[0]), "+f"(c[1]), "+f"(c[2]), "+f"(c[3])
        : "r"(a[0]), "r"(a[1]), "r"(a[2]), "r"(a[3]), "r"(b[0]), "r"(b[1]));
}
__device__ __forceinline__ void mma8(float* c, const uint32_t* a, const uint32_t* b) {
    asm volatile(
        "mma.sync.aligned.m16n8k8.row.col.f32.tf32.tf32.f32 "
        "{%0,%1,%2,%3}, {%4,%5,%6,%7}, {%8,%9}, {%0,%1,%2,%3};"
        : "+f"(c[0]), "+f"(c[1]), "+f"(c[2]), "+f"(c[3])
        : "r"(a[0]), "r"(a[1]), "r"(a[2]), "r"(a[3]), "r"(b[0]), "r"(b[1]));
}

// ---------------- prep: rowsum -> dis -> write fp16 dis*adj ----------------
__global__ void k_prep(const float* __restrict__ adj) {
    __shared__ float red[8];
    __shared__ float sdis;
    int row = blockIdx.x;
    const float4* p = (const float4*)(adj + (size_t)row * NN);
    float s = 0.f;
    for (int i = threadIdx.x; i < NN / 4; i += 256) {
        float4 v = p[i];
        s += (v.x + v.y) + (v.z + v.w);
    }
    #pragma unroll
    for (int o = 16; o > 0; o >>= 1) s += __shfl_xor_sync(0xffffffffu, s, o);
    if ((threadIdx.x & 31) == 0) red[threadIdx.x >> 5] = s;
    __syncthreads();
    if (threadIdx.x < 8) {
        s = red[threadIdx.x];
        #pragma unroll
        for (int o = 4; o > 0; o >>= 1) s += __shfl_xor_sync(0xffu, s, o);
        if (threadIdx.x == 0) {
            float d = (s > 0.f) ? rsqrtf(s) : 0.f;
            g_dis[row] = d;
            sdis = d;
        }
    }
    __syncthreads();
    float d = sdis;
    __half2* oh = (__half2*)(g_Ah + (size_t)row * NN);
    for (int i = threadIdx.x; i < NN / 4; i += 256) {
        float4 v = p[i];
        oh[2 * i]     = __floats2half2_rn(v.x * d, v.y * d);
        oh[2 * i + 1] = __floats2half2_rn(v.z * d, v.w * d);
    }
}

// tf32 W1 (k->n layout) + fp16 W2^T, W3^T ([fo][fi])
__global__ void k_prepW(const float* __restrict__ W1, const float* __restrict__ W2,
                        const float* __restrict__ W3) {
    int i = blockIdx.x * 256 + threadIdx.x;
    const float* W = (i < FD * FD) ? W1 : (i < 2 * FD * FD ? W2 : W3);
    int j = i & (FD * FD - 1);
    g_Wr[i] = __uint_as_float(cvt_rna(W[j]));
    if (i >= FD * FD) {
        int l = (i < 2 * FD * FD) ? 0 : 1;
        int fo = j >> 7, fi = j & 127;
        g_Wh[l][fo * FD + fi] = __float2half_rn(W[fi * FD + fo]);
    }
}

// ---------------- small GEMM (tf32) for layer 0: H1 = dis*lrelu(X@W1+b1) -> g_HhA ----
#define KC 32
#define SSTG 4
#define APAD 36
#define BPAD 136
#define A_TILE_F (128 * APAD)
#define B_TILE_F (KC * BPAD)
#define STAGE_F  (A_TILE_F + B_TILE_F)
#define SMALL_SMEM (SSTG * STAGE_F * 4)
#define NT 512

__global__ __launch_bounds__(NT, 1) void k_small(
    const float* __restrict__ Xext, const float* __restrict__ bias)
{
    extern __shared__ float sm[];
    int tid = threadIdx.x, lane = tid & 31, warp = tid >> 5;
    int warpM = (warp & 3) * 32, warpN = (warp >> 2) * 32;
    int grow = blockIdx.x * 128;
    const float* A = Xext + (size_t)grow * FD;
    const float* B = g_Wr;                       // W1

    float acc[2][4][4];
    #pragma unroll
    for (int mt = 0; mt < 2; mt++)
        #pragma unroll
        for (int nt = 0; nt < 4; nt++)
            #pragma unroll
            for (int i = 0; i < 4; i++) acc[mt][nt][i] = 0.f;

    auto issue = [&](int chunk) {
        float* as = sm + (chunk % SSTG) * STAGE_F;
        float* bs = as + A_TILE_F;
        uint32_t as_u = (uint32_t)__cvta_generic_to_shared(as);
        uint32_t bs_u = (uint32_t)__cvta_generic_to_shared(bs);
        int kbase = chunk * KC;
        #pragma unroll
        for (int j = 0; j < 2; j++) {
            int i = tid + NT * j;
            int r = i >> 3, c = (i & 7) << 2;
            cp16(as_u + (uint32_t)(r * APAD + c) * 4, A + (size_t)r * FD + kbase + c);
        }
        #pragma unroll
        for (int j = 0; j < 2; j++) {
            int i = tid + NT * j;
            int k = i >> 5, c = (i & 31) << 2;
            cp16(bs_u + (uint32_t)(k * BPAD + c) * 4, B + (size_t)(kbase + k) * FD + c);
        }
        asm volatile("cp.async.commit_group;");
    };

    int nch = FD / KC;
    #pragma unroll
    for (int p = 0; p < SSTG - 1; p++)
        if (p < nch) issue(p);

    for (int ch = 0; ch < nch; ch++) {
        asm volatile("cp.async.wait_group %0;" :: "n"(SSTG - 2));
        __syncthreads();
        if (ch + SSTG - 1 < nch) issue(ch + SSTG - 1);
        else asm volatile("cp.async.commit_group;");

        float* as = sm + (ch % SSTG) * STAGE_F;
        float* bs = as + A_TILE_F;
        #pragma unroll
        for (int kk = 0; kk < 4; kk++) {
            int kof = kk * 8;
            uint32_t af[2][4];
            uint32_t bf[4][2];
            #pragma unroll
            for (int mt = 0; mt < 2; mt++) {
                int r0 = warpM + mt * 16 + (lane >> 2);
                int kc = kof + (lane & 3);
                af[mt][0] = cvt_rna(as[r0 * APAD + kc]);
                af[mt][1] = cvt_rna(as[(r0 + 8) * APAD + kc]);
                af[mt][2] = cvt_rna(as[r0 * APAD + kc + 4]);
                af[mt][3] = cvt_rna(as[(r0 + 8) * APAD + kc + 4]);
            }
            #pragma unroll
            for (int nt = 0; nt < 4; nt++) {
                int nc = warpN + nt * 8 + (lane >> 2);
                int kr = kof + (lane & 3);
                bf[nt][0] = __float_as_uint(bs[kr * BPAD + nc]);
                bf[nt][1] = __float_as_uint(bs[(kr + 4) * BPAD + nc]);
            }
            #pragma unroll
            for (int mt = 0; mt < 2; mt++)
                #pragma unroll
                for (int nt = 0; nt < 4; nt++)
                    mma8(acc[mt][nt], af[mt], bf[nt]);
        }
    }

    #pragma unroll
    for (int mt = 0; mt < 2; mt++) {
        #pragma unroll
        for (int nt = 0; nt < 4; nt++) {
            int r0 = grow + warpM + mt * 16 + (lane >> 2);
            int n0 = warpN + nt * 8 + 2 * (lane & 3);
            #pragma unroll
            for (int i = 0; i < 4; i++) {
                int r = r0 + ((i >= 2) ? 8 : 0);
                int n = n0 + (i & 1);
                float v = acc[mt][nt][i];
                v += bias[n];
                v = (v > 0.f) ? v : 0.01f * v;
                v *= g_dis[r];
                int b = r >> 11, m = r & (NN - 1);
                g_HhA[((size_t)b * FD + n) * NN + m] = __float2half_rn(v);
            }
        }
    }
}

// ---------------- fused big GEMM, 2 CTAs/SM ----------------
// CTA tile 64x128, 256 threads, 8 warps 2Mx4N (warp 32x32), KCB=64, BSTG=3.
// Z = (dis*adj)@H (+X1 if layer==1). layer<2: H_next = fp16(dis*lrelu(Z@W+b)) fused.
#define KCB 64
#define BSTG 3
#define ATILE_BY 8192                      // 64 rows x 128B
#define BTILE_BY 16384                     // 128 rows x 128B
#define STAGE (ATILE_BY + BTILE_BY)        // 24576
#define WT_OFF (BSTG * STAGE)              // 73728
#define HT_OFF 16384                       // Ht reuses stage region post-mainloop
#define HT_PITCH 144                       // bytes per f-row (64 m x 2B + 16B pad)
#define BIG_SMEM (WT_OFF + 32768)          // 106496 (x2 CTAs = 212992 <= 232448)

__global__ __launch_bounds__(256, 2) void k_big(
    const float* __restrict__ bias_next, float* __restrict__ outext, int layer)
{
    extern __shared__ char smc[];
    uint32_t smb = (uint32_t)__cvta_generic_to_shared(smc);
    int tid = threadIdx.x, lane = tid & 31, warp = tid >> 5;
    int warpM = (warp & 1) * 32, warpN = (warp >> 1) * 32;
    int b = blockIdx.y;
    int mloc = blockIdx.x * 64;
    int grow = b * NN + mloc;

    const __half* Ah = g_Ah + (size_t)grow * NN;
    const __half* Bh = (layer == 1 ? g_HhB : g_HhA) + (size_t)b * FD * NN;
    __half* Hout = (layer == 0) ? g_HhB : g_HhA;

    float acc[2][4][4];
    #pragma unroll
    for (int mt = 0; mt < 2; mt++)
        #pragma unroll
        for (int nt = 0; nt < 4; nt++)
            #pragma unroll
            for (int i = 0; i < 4; i++) acc[mt][nt][i] = 0.f;

    // W^T preload (fp16 [fo][fi], two 64-fi 16KB k-blocks, SW128)
    if (layer < 2) {
        const __half* Wg = g_Wh[layer];
        #pragma unroll
        for (int j = 0; j < 8; j++) {
            int i = tid + 256 * j;
            int blk = i >> 10;
            int r = (i >> 3) & 127, c = i & 7;
            cp16(smb + WT_OFF + blk * 16384 + SWZ128((uint32_t)(r * 128 + c * 16)),
                 (const char*)(Wg + (size_t)r * FD + blk * 64) + c * 16);
        }
        asm volatile("cp.async.commit_group;");
    }

    auto issue = [&](int ch) {
        uint32_t base = smb + (ch % BSTG) * STAGE;
        int kb = ch * KCB;
        #pragma unroll
        for (int j = 0; j < 2; j++) {             // A: 64 rows x 8 segs = 512
            int i = tid + 256 * j;
            int r = i >> 3, c = i & 7;
            cp16(base + SWZ128((uint32_t)(r * 128 + c * 16)),
                 Ah + (size_t)r * NN + kb + c * 8);
        }
        #pragma unroll
        for (int j = 0; j < 4; j++) {             // B: 128 rows x 8 segs = 1024
            int i = tid + 256 * j;
            int r = i >> 3, c = i & 7;
            cp16(base + ATILE_BY + SWZ128((uint32_t)(r * 128 + c * 16)),
                 Bh + (size_t)r * NN + kb + c * 8);
        }
        asm volatile("cp.async.commit_group;");
    };

    const int nch = NN / KCB;                     // 32
    issue(0); issue(1);

    int mat = lane >> 3;
    for (int ch = 0; ch < nch; ch++) {
        asm volatile("cp.async.wait_group 1;");
        __syncthreads();
        if (ch + 2 < nch) issue(ch + 2);
        else asm volatile("cp.async.commit_group;");

        uint32_t base = smb + (ch % BSTG) * STAGE;
        #pragma unroll
        for (int s = 0; s < 4; s++) {             // four K=16 steps per chunk
            uint32_t cbase = (uint32_t)(s * 32);
            uint32_t ah[2][4];
            #pragma unroll
            for (int mt = 0; mt < 2; mt++) {
                int row = warpM + mt * 16 + ((mat & 1) << 3) + (lane & 7);
                uint32_t col = cbase + ((mat >> 1) << 4);
                LDSM4(ah[mt], base + SWZ128((uint32_t)(row * 128) + col));
            }
            uint32_t bf[4][2];
            #pragma unroll
            for (int p = 0; p < 2; p++) {
                int nrow = warpN + (p * 2 + (mat >> 1)) * 8 + (lane & 7);
                uint32_t col = cbase + ((mat & 1) << 4);
                uint32_t t[4];
                LDSM4(t, base + ATILE_BY + SWZ128((uint32_t)(nrow * 128) + col));
                bf[2 * p][0] = t[0]; bf[2 * p][1] = t[1];
                bf[2 * p + 1][0] = t[2]; bf[2 * p + 1][1] = t[3];
            }
            #pragma unroll
            for (int mt = 0; mt < 2; mt++)
                #pragma unroll
                for (int nt = 0; nt < 4; nt++)
                    mma_f16(acc[mt][nt], ah[mt], bf[nt]);
        }
    }

    if (layer == 2) {
        #pragma unroll
        for (int mt = 0; mt < 2; mt++)
            #pragma unroll
            for (int nt = 0; nt < 4; nt++) {
                int r0 = grow + warpM + mt * 16 + (lane >> 2);
                int n = warpN + nt * 8 + 2 * (lane & 3);
                #pragma unroll
                for (int h = 0; h < 2; h++) {
                    int r = r0 + h * 8;
                    float2 v = {acc[mt][nt][h * 2], acc[mt][nt][h * 2 + 1]};
                    *(float2*)(outext + (size_t)r * FD + n) = v;
                }
            }
        return;
    }

    // --- fused epilogue: Z -> smem fp16 (two 8KB f-blocks), small GEMM, H_next ---
    __syncthreads();                              // stage region free after this
    #pragma unroll
    for (int mt = 0; mt < 2; mt++)
        #pragma unroll
        for (int nt = 0; nt < 4; nt++) {
            int rl0 = warpM + mt * 16 + (lane >> 2);
            int f = warpN + nt * 8 + 2 * (lane & 3);
            #pragma unroll
            for (int h = 0; h < 2; h++) {
                int rl = rl0 + h * 8;
                float zx = acc[mt][nt][h * 2], zy = acc[mt][nt][h * 2 + 1];
                if (layer == 1) {
                    __half2 rv = *(const __half2*)(g_Xh1 + (size_t)(grow + rl) * FD + f);
                    float2 rf = __half22float2(rv);
                    zx += rf.x; zy += rf.y;
                }
                __half2 hz = __floats2half2_rn(zx, zy);
                uint32_t zo = (uint32_t)((f >> 6) << 13)
                            + SWZ128((uint32_t)(rl * 128 + (f & 63) * 2));
                *(__half2*)(smc + zo) = hz;
                if (layer == 0)
                    *(__half2*)(g_Xh1 + (size_t)(grow + rl) * FD + f) = hz;
            }
        }
    asm volatile("cp.async.wait_group 0;");       // W tile resident
    __syncthreads();

    #pragma unroll
    for (int mt = 0; mt < 2; mt++)
        #pragma unroll
        for (int nt = 0; nt < 4; nt++)
            #pragma unroll
            for (int i = 0; i < 4; i++) acc[mt][nt][i] = 0.f;

    #pragma unroll
    for (int wz = 0; wz < 2; wz++) {              // two 64-fi K-blocks
        uint32_t za = smb + wz * 8192;
        uint32_t wa = smb + WT_OFF + wz * 16384;
        #pragma unroll
        for (int s = 0; s < 4; s++) {
            uint32_t ah[2][4];
            #pragma unroll
            for (int mt = 0; mt < 2; mt++) {
                int row = warpM + mt * 16 + ((mat & 1) << 3) + (lane & 7);
                uint32_t col = (uint32_t)(s * 32 + ((mat >> 1) << 4));
                LDSM4(ah[mt], za + SWZ128((uint32_t)(row * 128) + col));
            }
            uint32_t bf[4][2];
            #pragma unroll
            for (int p = 0; p < 2; p++) {
                int nrow = warpN + (p * 2 + (mat >> 1)) * 8 + (lane & 7);
                uint32_t col = (uint32_t)(s * 32 + ((mat & 1) << 4));
                uint32_t t[4];
                LDSM4(t, wa + SWZ128((uint32_t)(nrow * 128) + col));
                bf[2 * p][0] = t[0]; bf[2 * p][1] = t[1];
                bf[2 * p + 1][0] = t[2]; bf[2 * p + 1][1] = t[3];
            }
            #pragma unroll
            for (int mt = 0; mt < 2; mt++)
                #pragma unroll
                for (int nt = 0; nt < 4; nt++)
                    mma_f16(acc[mt][nt], ah[mt], bf[nt]);
        }
    }

    // epilogue2: H = fp16(dis * lrelu(acc + bias)) -> Ht smem [f][m]
    #pragma unroll
    for (int mt = 0; mt < 2; mt++)
        #pragma unroll
        for (int nt = 0; nt < 4; nt++) {
            int rl0 = warpM + mt * 16 + (lane >> 2);
            int f = warpN + nt * 8 + 2 * (lane & 3);
            float bx = bias_next[f], by = bias_next[f + 1];
            #pragma unroll
            for (int h = 0; h < 2; h++) {
                int rl = rl0 + h * 8;
                float d = g_dis[grow + rl];
                float vx = acc[mt][nt][h * 2] + bx;
                float vy = acc[mt][nt][h * 2 + 1] + by;
                vx = (vx > 0.f) ? vx : 0.01f * vx;
                vy = (vy > 0.f) ? vy : 0.01f * vy;
                *(__half*)(smc + HT_OFF + f * HT_PITCH + rl * 2) = __float2half_rn(vx * d);
                *(__half*)(smc + HT_OFF + (f + 1) * HT_PITCH + rl * 2) = __float2half_rn(vy * d);
            }
        }
    __syncthreads();

    {   // coalesced write: 128 f-rows x 64 m x 2B
        int f = tid >> 1, seg = tid & 1;
        const char* src = smc + HT_OFF + f * HT_PITCH + seg * 64;
        __half* dst = Hout + ((size_t)b * FD + f) * NN + mloc + seg * 32;
        #pragma unroll
        for (int j = 0; j < 4; j++)
            *(float4*)(dst + j * 8) = *(const float4*)(src + j * 16);
    }
}

// ---------------- launch ----------------
extern "C" void kernel_launch(void* const* d_in, const int* in_sizes, int n_in,
                              void* d_out, int out_size) {
    (void)in_sizes; (void)n_in; (void)out_size;
    const float* X   = (const float*)d_in[0];
    const float* adj = (const float*)d_in[1];
    const float* W1  = (const float*)d_in[2];
    const float* b1  = (const float*)d_in[3];
    const float* W2  = (const float*)d_in[4];
    const float* b2  = (const float*)d_in[5];
    const float* W3  = (const float*)d_in[6];
    const float* b3  = (const float*)d_in[7];
    float* out = (float*)d_out;

    cudaFuncSetAttribute(k_small, cudaFuncAttributeMaxDynamicSharedMemorySize, SMALL_SMEM);
    cudaFuncSetAttribute(k_big,   cudaFuncAttributeMaxDynamicSharedMemorySize, BIG_SMEM);

    k_prep<<<NB * NN, 256>>>(adj);
    k_prepW<<<(3 * FD * FD) / 256, 256>>>(W1, W2, W3);

    k_small<<<16384 / 128, NT, SMALL_SMEM>>>(X, b1);           // H1 -> g_HhA
    k_big<<<dim3(NN / 64, NB), 256, BIG_SMEM>>>(b2, out, 0);   // Z1, H2 -> g_HhB, X1
    k_big<<<dim3(NN / 64, NB), 256, BIG_SMEM>>>(b3, out, 1);   // Z2(+X1), H3 -> g_HhA
    k_big<<<dim3(NN / 64, NB), 256, BIG_SMEM>>>(b1, out, 2);   // out = A'@H3
}

// round 12
// speedup vs baseline: 1.4418x; 1.4418x over previous
#include <cuda_runtime.h>
#include <cuda_fp16.h>
#include <cstdint>
#include <cstddef>

#define NB 8
#define NN 2048
#define FD 128

// ---------------- device scratch (no cudaMalloc allowed) ----------------
__device__ float g_dis[NB * NN];
__device__ __half g_Ah[(size_t)NB * NN * NN];   // fp16(dis[n]*adj[n,m])
__device__ __half g_HhA[NB * FD * NN];          // H transposed [b][f][m], buffer A
__device__ __half g_HhB[NB * FD * NN];          // buffer B
__device__ __half g_Xh1[NB * NN * FD];          // fp16 X1 (for residual)
__device__ float g_Wr[3 * FD * FD];             // tf32 weights (layer-0 small GEMM)
__device__ __half g_Wh[2][FD * FD];             // fp16 W^T for W2, W3: [fo][fi]
__device__ float g_part[(size_t)128 * 16384];   // split-K partials: 128 tiles x 128x128 f32
__device__ unsigned g_flag[3 * 128];            // per-layer per-tile ready flags

// ---------------- helpers ----------------
__device__ __forceinline__ uint32_t cvt_rna(float x) {
    uint32_t r;
    asm("cvt.rna.tf32.f32 %0, %1;" : "=r"(r) : "f"(x));
    return r;
}
__device__ __forceinline__ void cp16(uint32_t smem_dst, const void* gsrc) {
    asm volatile("cp.async.cg.shared.global [%0], [%1], 16;" :: "r"(smem_dst), "l"(gsrc));
}
#define SWZ128(o) ((o) ^ (((o) >> 3) & 0x70))

#define LDSM4(R, a) \
    asm volatile("ldmatrix.sync.aligned.m8n8.x4.shared.b16 {%0,%1,%2,%3}, [%4];" \
        : "=r"((R)[0]), "=r"((R)[1]), "=r"((R)[2]), "=r"((R)[3]) : "r"(a))

__device__ __forceinline__ void mma_f16(float* c, const uint32_t* a, const uint32_t* b) {
    asm volatile(
        "mma.sync.aligned.m16n8k16.row.col.f32.f16.f16.f32 "
        "{%0,%1,%2,%3}, {%4,%5,%6,%7}, {%8,%9}, {%0,%1,%2,%3};"
        : "+f"(c[0]), "+f"(c[1]), "+f"(c[2]), "+f"(c[3])
        : "r"(a[0]), "r"(a[1]), "r"(a[2]), "r"(a[3]), "r"(b[0]), "r"(b[1]));
}
__device__ __forceinline__ void mma8(float* c, const uint32_t* a, const uint32_t* b) {
    asm volatile(
        "mma.sync.aligned.m16n8k8.row.col.f32.tf32.tf32.f32 "
        "{%0,%1,%2,%3}, {%4,%5,%6,%7}, {%8,%9}, {%0,%1,%2,%3};"
        : "+f"(c[0]), "+f"(c[1]), "+f"(c[2]), "+f"(c[3])
        : "r"(a[0]), "r"(a[1]), "r"(a[2]), "r"(a[3]), "r"(b[0]), "r"(b[1]));
}

// ---------------- prep: rowsum -> dis -> write fp16 dis*adj ----------------
__global__ void k_prep(const float* __restrict__ adj) {
    __shared__ float red[8];
    __shared__ float sdis;
    int row = blockIdx.x;
    const float4* p = (const float4*)(adj + (size_t)row * NN);
    float s = 0.f;
    for (int i = threadIdx.x; i < NN / 4; i += 256) {
        float4 v = p[i];
        s += (v.x + v.y) + (v.z + v.w);
    }
    #pragma unroll
    for (int o = 16; o > 0; o >>= 1) s += __shfl_xor_sync(0xffffffffu, s, o);
    if ((threadIdx.x & 31) == 0) red[threadIdx.x >> 5] = s;
    __syncthreads();
    if (threadIdx.x < 8) {
        s = red[threadIdx.x];
        #pragma unroll
        for (int o = 4; o > 0; o >>= 1) s += __shfl_xor_sync(0xffu, s, o);
        if (threadIdx.x == 0) {
            float d = (s > 0.f) ? rsqrtf(s) : 0.f;
            g_dis[row] = d;
            sdis = d;
        }
    }
    __syncthreads();
    float d = sdis;
    __half2* oh = (__half2*)(g_Ah + (size_t)row * NN);
    for (int i = threadIdx.x; i < NN / 4; i += 256) {
        float4 v = p[i];
        oh[2 * i]     = __floats2half2_rn(v.x * d, v.y * d);
        oh[2 * i + 1] = __floats2half2_rn(v.z * d, v.w * d);
    }
}

// tf32 W1 + fp16 W2^T, W3^T; also zero split-K flags (every call -> graph-deterministic)
__global__ void k_prepW(const float* __restrict__ W1, const float* __restrict__ W2,
                        const float* __restrict__ W3) {
    int i = blockIdx.x * 256 + threadIdx.x;
    if (i < 3 * 128) g_flag[i] = 0u;
    const float* W = (i < FD * FD) ? W1 : (i < 2 * FD * FD ? W2 : W3);
    int j = i & (FD * FD - 1);
    g_Wr[i] = __uint_as_float(cvt_rna(W[j]));
    if (i >= FD * FD) {
        int l = (i < 2 * FD * FD) ? 0 : 1;
        int fo = j >> 7, fi = j & 127;
        g_Wh[l][fo * FD + fi] = __float2half_rn(W[fi * FD + fo]);
    }
}

// ---------------- small GEMM (tf32) for layer 0: H1 = dis*lrelu(X@W1+b1) -> g_HhA ----
#define KC 32
#define SSTG 4
#define APAD 36
#define BPAD 136
#define A_TILE_F (128 * APAD)
#define B_TILE_F (KC * BPAD)
#define STAGE_F  (A_TILE_F + B_TILE_F)
#define SMALL_SMEM (SSTG * STAGE_F * 4)
#define NT 512

__global__ __launch_bounds__(NT, 1) void k_small(
    const float* __restrict__ Xext, const float* __restrict__ bias)
{
    extern __shared__ float sm[];
    int tid = threadIdx.x, lane = tid & 31, warp = tid >> 5;
    int warpM = (warp & 3) * 32, warpN = (warp >> 2) * 32;
    int grow = blockIdx.x * 128;
    const float* A = Xext + (size_t)grow * FD;
    const float* B = g_Wr;

    float acc[2][4][4];
    #pragma unroll
    for (int mt = 0; mt < 2; mt++)
        #pragma unroll
        for (int nt = 0; nt < 4; nt++)
            #pragma unroll
            for (int i = 0; i < 4; i++) acc[mt][nt][i] = 0.f;

    auto issue = [&](int chunk) {
        float* as = sm + (chunk % SSTG) * STAGE_F;
        float* bs = as + A_TILE_F;
        uint32_t as_u = (uint32_t)__cvta_generic_to_shared(as);
        uint32_t bs_u = (uint32_t)__cvta_generic_to_shared(bs);
        int kbase = chunk * KC;
        #pragma unroll
        for (int j = 0; j < 2; j++) {
            int i = tid + NT * j;
            int r = i >> 3, c = (i & 7) << 2;
            cp16(as_u + (uint32_t)(r * APAD + c) * 4, A + (size_t)r * FD + kbase + c);
        }
        #pragma unroll
        for (int j = 0; j < 2; j++) {
            int i = tid + NT * j;
            int k = i >> 5, c = (i & 31) << 2;
            cp16(bs_u + (uint32_t)(k * BPAD + c) * 4, B + (size_t)(kbase + k) * FD + c);
        }
        asm volatile("cp.async.commit_group;");
    };

    int nch = FD / KC;
    #pragma unroll
    for (int p = 0; p < SSTG - 1; p++)
        if (p < nch) issue(p);

    for (int ch = 0; ch < nch; ch++) {
        asm volatile("cp.async.wait_group %0;" :: "n"(SSTG - 2));
        __syncthreads();
        if (ch + SSTG - 1 < nch) issue(ch + SSTG - 1);
        else asm volatile("cp.async.commit_group;");

        float* as = sm + (ch % SSTG) * STAGE_F;
        float* bs = as + A_TILE_F;
        #pragma unroll
        for (int kk = 0; kk < 4; kk++) {
            int kof = kk * 8;
            uint32_t af[2][4];
            uint32_t bf[4][2];
            #pragma unroll
            for (int mt = 0; mt < 2; mt++) {
                int r0 = warpM + mt * 16 + (lane >> 2);
                int kc = kof + (lane & 3);
                af[mt][0] = cvt_rna(as[r0 * APAD + kc]);
                af[mt][1] = cvt_rna(as[(r0 + 8) * APAD + kc]);
                af[mt][2] = cvt_rna(as[r0 * APAD + kc + 4]);
                af[mt][3] = cvt_rna(as[(r0 + 8) * APAD + kc + 4]);
            }
            #pragma unroll
            for (int nt = 0; nt < 4; nt++) {
                int nc = warpN + nt * 8 + (lane >> 2);
                int kr = kof + (lane & 3);
                bf[nt][0] = __float_as_uint(bs[kr * BPAD + nc]);
                bf[nt][1] = __float_as_uint(bs[(kr + 4) * BPAD + nc]);
            }
            #pragma unroll
            for (int mt = 0; mt < 2; mt++)
                #pragma unroll
                for (int nt = 0; nt < 4; nt++)
                    mma8(acc[mt][nt], af[mt], bf[nt]);
        }
    }

    #pragma unroll
    for (int mt = 0; mt < 2; mt++) {
        #pragma unroll
        for (int nt = 0; nt < 4; nt++) {
            int r0 = grow + warpM + mt * 16 + (lane >> 2);
            int n0 = warpN + nt * 8 + 2 * (lane & 3);
            #pragma unroll
            for (int i = 0; i < 4; i++) {
                int r = r0 + ((i >= 2) ? 8 : 0);
                int n = n0 + (i & 1);
                float v = acc[mt][nt][i];
                v += bias[n];
                v = (v > 0.f) ? v : 0.01f * v;
                v *= g_dis[r];
                int b = r >> 11, m = r & (NN - 1);
                g_HhA[((size_t)b * FD + n) * NN + m] = __float2half_rn(v);
            }
        }
    }
}

// ---------------- fused big GEMM, split-K2, 2 CTAs/SM ----------------
// CTA tile 128x128xK1024, 256 threads, 8 warps 4Mx2N (warp 32x64), KCB=64, BSTG=3.
// khalf 0: writes f32 partial + flag, exits. khalf 1: combines, fused epilogue.
#define KCB 64
#define BSTG 3
#define ATILE_BY 16384                     // 128 rows x 128B
#define STAGE (2 * ATILE_BY)               // 32768
#define ZT_OFF 32768                       // Z reuses stage-1 region post-mainloop
#define HT_PITCH 272
#define BIG_SMEM (BSTG * STAGE)            // 98304 (x2 CTAs = 196608)

__global__ __launch_bounds__(256, 2) void k_big(
    const float* __restrict__ bias_next, float* __restrict__ outext, int layer)
{
    extern __shared__ char smc[];
    uint32_t smb = (uint32_t)__cvta_generic_to_shared(smc);
    int tid = threadIdx.x, lane = tid & 31, warp = tid >> 5;
    int warpM = (warp & 3) * 32, warpN = (warp >> 2) * 64;
    int khalf = blockIdx.x, mtile = blockIdx.y, b = blockIdx.z;
    int mloc = mtile * 128;
    int grow = b * NN + mloc;
    int tileid = b * 16 + mtile;
    unsigned* flag = &g_flag[layer * 128 + tileid];
    float* part = g_part + (size_t)tileid * 16384;

    const __half* Ah = g_Ah + (size_t)grow * NN + khalf * 1024;
    const __half* Bh = (layer == 1 ? g_HhB : g_HhA) + (size_t)b * FD * NN + khalf * 1024;
    __half* Hout = (layer == 0) ? g_HhB : g_HhA;

    float acc[2][8][4];
    #pragma unroll
    for (int mt = 0; mt < 2; mt++)
        #pragma unroll
        for (int nt = 0; nt < 8; nt++)
            #pragma unroll
            for (int i = 0; i < 4; i++) acc[mt][nt][i] = 0.f;

    auto issue = [&](int ch) {
        uint32_t base = smb + (ch % BSTG) * STAGE;
        int kb = ch * KCB;
        #pragma unroll
        for (int j = 0; j < 4; j++) {              // A: 1024 16B segs
            int i = tid + 256 * j;
            int r = i >> 3, c = i & 7;
            uint32_t dsw = SWZ128((uint32_t)(r * 128 + c * 16));
            size_t so = (size_t)r * NN + kb + c * 8;
            cp16(base + dsw,            Ah + so);
            cp16(base + ATILE_BY + dsw, Bh + so);
        }
        asm volatile("cp.async.commit_group;");
    };

    const int nch = 1024 / KCB;                    // 16
    issue(0); issue(1);

    int mat = lane >> 3;
    for (int ch = 0; ch < nch; ch++) {
        asm volatile("cp.async.wait_group 1;");
        __syncthreads();
        if (ch + 2 < nch) issue(ch + 2);
        else asm volatile("cp.async.commit_group;");

        uint32_t base = smb + (ch % BSTG) * STAGE;
        #pragma unroll
        for (int s = 0; s < 4; s++) {              // four K=16 steps per chunk
            uint32_t cbase = (uint32_t)(s * 32);
            uint32_t ah[2][4];
            #pragma unroll
            for (int mt = 0; mt < 2; mt++) {
                int row = warpM + mt * 16 + ((mat & 1) << 3) + (lane & 7);
                uint32_t col = cbase + ((mat >> 1) << 4);
                LDSM4(ah[mt], base + SWZ128((uint32_t)(row * 128) + col));
            }
            uint32_t bf[8][2];
            #pragma unroll
            for (int p = 0; p < 4; p++) {
                int nrow = warpN + (p * 2 + (mat >> 1)) * 8 + (lane & 7);
                uint32_t col = cbase + ((mat & 1) << 4);
                uint32_t t[4];
                LDSM4(t, base + ATILE_BY + SWZ128((uint32_t)(nrow * 128) + col));
                bf[2 * p][0] = t[0]; bf[2 * p][1] = t[1];
                bf[2 * p + 1][0] = t[2]; bf[2 * p + 1][1] = t[3];
            }
            #pragma unroll
            for (int mt = 0; mt < 2; mt++)
                #pragma unroll
                for (int nt = 0; nt < 8; nt++)
                    mma_f16(acc[mt][nt], ah[mt], bf[nt]);
        }
    }

    if (khalf == 0) {
        // publish partial (coalesced: q*256 + tid), release flag, exit
        #pragma unroll
        for (int mt = 0; mt < 2; mt++)
            #pragma unroll
            for (int nt = 0; nt < 8; nt++)
                #pragma unroll
                for (int i = 0; i < 4; i++) {
                    int q = (mt * 8 + nt) * 4 + i;
                    part[q * 256 + tid] = acc[mt][nt][i];
                }
        __threadfence();
        __syncthreads();
        if (tid == 0) atomicExch(flag, 1u);
        return;
    }

    // ---- khalf == 1: preload W during the wait, combine, fused epilogue ----
    if (layer < 2) {
        const __half* Wg = g_Wh[layer];
        #pragma unroll
        for (int j = 0; j < 8; j++) {              // W^T: two 16KB k-blocks at smb+0
            int i = tid + 256 * j;
            int blk = i >> 10;
            int r = (i >> 3) & 127, c = i & 7;
            cp16(smb + blk * 16384 + SWZ128((uint32_t)(r * 128 + c * 16)),
                 Wg + (size_t)r * FD + blk * 64 + c * 8);
        }
        asm volatile("cp.async.commit_group;");
    }
    if (tid == 0) {
        while (atomicAdd(flag, 0u) == 0u) { }
    }
    __syncthreads();
    __threadfence();
    #pragma unroll
    for (int mt = 0; mt < 2; mt++)
        #pragma unroll
        for (int nt = 0; nt < 8; nt++)
            #pragma unroll
            for (int i = 0; i < 4; i++) {
                int q = (mt * 8 + nt) * 4 + i;
                acc[mt][nt][i] += part[q * 256 + tid];
            }

    if (layer == 2) {
        #pragma unroll
        for (int mt = 0; mt < 2; mt++)
            #pragma unroll
            for (int nt = 0; nt < 8; nt++) {
                int r0 = grow + warpM + mt * 16 + (lane >> 2);
                int n = warpN + nt * 8 + 2 * (lane & 3);
                #pragma unroll
                for (int h = 0; h < 2; h++) {
                    int r = r0 + h * 8;
                    float2 v = {acc[mt][nt][h * 2], acc[mt][nt][h * 2 + 1]};
                    *(float2*)(outext + (size_t)r * FD + n) = v;
                }
            }
        return;
    }

    // Z -> smem fp16 (two 16KB f-blocks at ZT_OFF), +X1 logic
    #pragma unroll
    for (int mt = 0; mt < 2; mt++)
        #pragma unroll
        for (int nt = 0; nt < 8; nt++) {
            int rl0 = warpM + mt * 16 + (lane >> 2);
            int f = warpN + nt * 8 + 2 * (lane & 3);
            #pragma unroll
            for (int h = 0; h < 2; h++) {
                int rl = rl0 + h * 8;
                float zx = acc[mt][nt][h * 2], zy = acc[mt][nt][h * 2 + 1];
                if (layer == 1) {
                    __half2 rv = *(const __half2*)(g_Xh1 + (size_t)(grow + rl) * FD + f);
                    float2 rf = __half22float2(rv);
                    zx += rf.x; zy += rf.y;
                }
                __half2 hz = __floats2half2_rn(zx, zy);
                uint32_t zo = ZT_OFF + (uint32_t)((f >> 6) << 14)
                            + SWZ128((uint32_t)(rl * 128 + (f & 63) * 2));
                *(__half2*)(smc + zo) = hz;
                if (layer == 0)
                    *(__half2*)(g_Xh1 + (size_t)(grow + rl) * FD + f) = hz;
            }
        }
    asm volatile("cp.async.wait_group 0;");        // W resident
    __syncthreads();

    #pragma unroll
    for (int mt = 0; mt < 2; mt++)
        #pragma unroll
        for (int nt = 0; nt < 8; nt++)
            #pragma unroll
            for (int i = 0; i < 4; i++) acc[mt][nt][i] = 0.f;

    #pragma unroll
    for (int wz = 0; wz < 2; wz++) {               // two 64-fi K-blocks
        uint32_t za = smb + ZT_OFF + wz * 16384;
        uint32_t wa = smb + wz * 16384;
        #pragma unroll
        for (int s = 0; s < 4; s++) {
            uint32_t ah[2][4];
            #pragma unroll
            for (int mt = 0; mt < 2; mt++) {
                int row = warpM + mt * 16 + ((mat & 1) << 3) + (lane & 7);
                uint32_t col = (uint32_t)(s * 32 + ((mat >> 1) << 4));
                LDSM4(ah[mt], za + SWZ128((uint32_t)(row * 128) + col));
            }
            uint32_t bf[8][2];
            #pragma unroll
            for (int p = 0; p < 4; p++) {
                int nrow = warpN + (p * 2 + (mat >> 1)) * 8 + (lane & 7);
                uint32_t col = (uint32_t)(s * 32 + ((mat & 1) << 4));
                uint32_t t[4];
                LDSM4(t, wa + SWZ128((uint32_t)(nrow * 128) + col));
                bf[2 * p][0] = t[0]; bf[2 * p][1] = t[1];
                bf[2 * p + 1][0] = t[2]; bf[2 * p + 1][1] = t[3];
            }
            #pragma unroll
            for (int mt = 0; mt < 2; mt++)
                #pragma unroll
                for (int nt = 0; nt < 8; nt++)
                    mma_f16(acc[mt][nt], ah[mt], bf[nt]);
        }
    }
    __syncthreads();                               // Z reads done; reuse region for Ht

    // epilogue2: H = fp16(dis*lrelu(acc+bias)) -> Ht smem [f][m] at ZT_OFF
    #pragma unroll
    for (int mt = 0; mt < 2; mt++)
        #pragma unroll
        for (int nt = 0; nt < 8; nt++) {
            int rl0 = warpM + mt * 16 + (lane >> 2);
            int f = warpN + nt * 8 + 2 * (lane & 3);
            float bx = bias_next[f], by = bias_next[f + 1];
            #pragma unroll
            for (int h = 0; h < 2; h++) {
                int rl = rl0 + h * 8;
                float d = g_dis[grow + rl];
                float vx = acc[mt][nt][h * 2] + bx;
                float vy = acc[mt][nt][h * 2 + 1] + by;
                vx = (vx > 0.f) ? vx : 0.01f * vx;
                vy = (vy > 0.f) ? vy : 0.01f * vy;
                *(__half*)(smc + ZT_OFF + f * HT_PITCH + rl * 2) = __float2half_rn(vx * d);
                *(__half*)(smc + ZT_OFF + (f + 1) * HT_PITCH + rl * 2) = __float2half_rn(vy * d);
            }
        }
    __syncthreads();

    {   // coalesced write: 128 f-rows x 128 m x 2B
        int f = tid >> 1, seg = tid & 1;
        const char* src = smc + ZT_OFF + f * HT_PITCH + seg * 128;
        __half* dst = Hout + ((size_t)b * FD + f) * NN + mloc + seg * 64;
        #pragma unroll
        for (int j = 0; j < 8; j++)
            *(float4*)(dst + j * 8) = *(const float4*)(src + j * 16);
    }
}

// ---------------- launch ----------------
extern "C" void kernel_launch(void* const* d_in, const int* in_sizes, int n_in,
                              void* d_out, int out_size) {
    (void)in_sizes; (void)n_in; (void)out_size;
    const float* X   = (const float*)d_in[0];
    const float* adj = (const float*)d_in[1];
    const float* W1  = (const float*)d_in[2];
    const float* b1  = (const float*)d_in[3];
    const float* W2  = (const float*)d_in[4];
    const float* b2  = (const float*)d_in[5];
    const float* W3  = (const float*)d_in[6];
    const float* b3  = (const float*)d_in[7];
    float* out = (float*)d_out;

    cudaFuncSetAttribute(k_small, cudaFuncAttributeMaxDynamicSharedMemorySize, SMALL_SMEM);
    cudaFuncSetAttribute(k_big,   cudaFuncAttributeMaxDynamicSharedMemorySize, BIG_SMEM);

    k_prep<<<NB * NN, 256>>>(adj);
    k_prepW<<<(3 * FD * FD) / 256, 256>>>(W1, W2, W3);

    k_small<<<16384 / 128, NT, SMALL_SMEM>>>(X, b1);              // H1 -> g_HhA
    k_big<<<dim3(2, 16, NB), 256, BIG_SMEM>>>(b2, out, 0);        // Z1, H2 -> g_HhB, X1
    k_big<<<dim3(2, 16, NB), 256, BIG_SMEM>>>(b3, out, 1);        // Z2(+X1), H3 -> g_HhA
    k_big<<<dim3(2, 16, NB), 256, BIG_SMEM>>>(b1, out, 2);        // out = A'@H3
}

// round 13
// speedup vs baseline: 1.4439x; 1.0015x over previous
#include <cuda_runtime.h>
#include <cuda_fp16.h>
#include <cstdint>
#include <cstddef>

#define NB 8
#define NN 2048
#define FD 128

// ---------------- device scratch (no cudaMalloc allowed) ----------------
__device__ float g_dis[NB * NN];
__device__ __half g_Ah[(size_t)NB * NN * NN];   // fp16(dis[n]*adj[n,m])
__device__ __half g_HhA[NB * FD * NN];          // H transposed [b][f][m], buffer A
__device__ __half g_HhB[NB * FD * NN];          // buffer B
__device__ __half g_Xh1[NB * NN * FD];          // fp16 X1 (for residual)
__device__ float g_Wr[3 * FD * FD];             // tf32 weights (layer-0 small GEMM)
__device__ __half g_Wh[2][FD * FD];             // fp16 W^T for W2, W3: [fo][fi]

// ---------------- helpers ----------------
__device__ __forceinline__ uint32_t cvt_rna(float x) {
    uint32_t r;
    asm("cvt.rna.tf32.f32 %0, %1;" : "=r"(r) : "f"(x));
    return r;
}
__device__ __forceinline__ void cp16(uint32_t smem_dst, const void* gsrc) {
    asm volatile("cp.async.cg.shared.global [%0], [%1], 16;" :: "r"(smem_dst), "l"(gsrc));
}
#define SWZ128(o) ((o) ^ (((o) >> 3) & 0x70))

#define LDSM4(R, a) \
    asm volatile("ldmatrix.sync.aligned.m8n8.x4.shared.b16 {%0,%1,%2,%3}, [%4];" \
        : "=r"((R)[0]), "=r"((R)[1]), "=r"((R)[2]), "=r"((R)[3]) : "r"(a))

__device__ __forceinline__ void mma_f16(float* c, const uint32_t* a, const uint32_t* b) {
    asm volatile(
        "mma.sync.aligned.m16n8k16.row.col.f32.f16.f16.f32 "
        "{%0,%1,%2,%3}, {%4,%5,%6,%7}, {%8,%9}, {%0,%1,%2,%3};"
        : "+f"(c[0]), "+f"(c[1]), "+f"(c[2]), "+f"(c[3])
        : "r"(a[0]), "r"(a[1]), "r"(a[2]), "r"(a[3]), "r"(b[0]), "r"(b[1]));
}
__device__ __forceinline__ void mma8(float* c, const uint32_t* a, const uint32_t* b) {
    asm volatile(
        "mma.sync.aligned.m16n8k8.row.col.f32.tf32.tf32.f32 "
        "{%0,%1,%2,%3}, {%4,%5,%6,%7}, {%8,%9}, {%0,%1,%2,%3};"
        : "+f"(c[0]), "+f"(c[1]), "+f"(c[2]), "+f"(c[3])
        : "r"(a[0]), "r"(a[1]), "r"(a[2]), "r"(a[3]), "r"(b[0]), "r"(b[1]));
}

// ---------------- prep: rowsum -> dis -> write fp16 dis*adj ----------------
__global__ void k_prep(const float* __restrict__ adj) {
    __shared__ float red[8];
    __shared__ float sdis;
    int row = blockIdx.x;
    const float4* p = (const float4*)(adj + (size_t)row * NN);
    float s = 0.f;
    for (int i = threadIdx.x; i < NN / 4; i += 256) {
        float4 v = p[i];
        s += (v.x + v.y) + (v.z + v.w);
    }
    #pragma unroll
    for (int o = 16; o > 0; o >>= 1) s += __shfl_xor_sync(0xffffffffu, s, o);
    if ((threadIdx.x & 31) == 0) red[threadIdx.x >> 5] = s;
    __syncthreads();
    if (threadIdx.x < 8) {
        s = red[threadIdx.x];
        #pragma unroll
        for (int o = 4; o > 0; o >>= 1) s += __shfl_xor_sync(0xffu, s, o);
        if (threadIdx.x == 0) {
            float d = (s > 0.f) ? rsqrtf(s) : 0.f;
            g_dis[row] = d;
            sdis = d;
        }
    }
    __syncthreads();
    float d = sdis;
    __half2* oh = (__half2*)(g_Ah + (size_t)row * NN);
    for (int i = threadIdx.x; i < NN / 4; i += 256) {
        float4 v = p[i];
        oh[2 * i]     = __floats2half2_rn(v.x * d, v.y * d);
        oh[2 * i + 1] = __floats2half2_rn(v.z * d, v.w * d);
    }
}

// tf32 W1 (k->n) + fp16 W2^T, W3^T ([fo][fi])
__global__ void k_prepW(const float* __restrict__ W1, const float* __restrict__ W2,
                        const float* __restrict__ W3) {
    int i = blockIdx.x * 256 + threadIdx.x;
    const float* W = (i < FD * FD) ? W1 : (i < 2 * FD * FD ? W2 : W3);
    int j = i & (FD * FD - 1);
    g_Wr[i] = __uint_as_float(cvt_rna(W[j]));
    if (i >= FD * FD) {
        int l = (i < 2 * FD * FD) ? 0 : 1;
        int fo = j >> 7, fi = j & 127;
        g_Wh[l][fo * FD + fi] = __float2half_rn(W[fi * FD + fo]);
    }
}

// ---------------- small GEMM (tf32) for layer 0: H1 = dis*lrelu(X@W1+b1) -> g_HhA ----
#define KC 32
#define SSTG 4
#define APAD 36
#define BPAD 136
#define A_TILE_F (128 * APAD)
#define B_TILE_F (KC * BPAD)
#define STAGE_F  (A_TILE_F + B_TILE_F)
#define SMALL_SMEM (SSTG * STAGE_F * 4)
#define NT 512

__global__ __launch_bounds__(NT, 1) void k_small(
    const float* __restrict__ Xext, const float* __restrict__ bias)
{
    extern __shared__ float sm[];
    int tid = threadIdx.x, lane = tid & 31, warp = tid >> 5;
    int warpM = (warp & 3) * 32, warpN = (warp >> 2) * 32;
    int grow = blockIdx.x * 128;
    const float* A = Xext + (size_t)grow * FD;
    const float* B = g_Wr;

    float acc[2][4][4];
    #pragma unroll
    for (int mt = 0; mt < 2; mt++)
        #pragma unroll
        for (int nt = 0; nt < 4; nt++)
            #pragma unroll
            for (int i = 0; i < 4; i++) acc[mt][nt][i] = 0.f;

    auto issue = [&](int chunk) {
        float* as = sm + (chunk % SSTG) * STAGE_F;
        float* bs = as + A_TILE_F;
        uint32_t as_u = (uint32_t)__cvta_generic_to_shared(as);
        uint32_t bs_u = (uint32_t)__cvta_generic_to_shared(bs);
        int kbase = chunk * KC;
        #pragma unroll
        for (int j = 0; j < 2; j++) {
            int i = tid + NT * j;
            int r = i >> 3, c = (i & 7) << 2;
            cp16(as_u + (uint32_t)(r * APAD + c) * 4, A + (size_t)r * FD + kbase + c);
        }
        #pragma unroll
        for (int j = 0; j < 2; j++) {
            int i = tid + NT * j;
            int k = i >> 5, c = (i & 31) << 2;
            cp16(bs_u + (uint32_t)(k * BPAD + c) * 4, B + (size_t)(kbase + k) * FD + c);
        }
        asm volatile("cp.async.commit_group;");
    };

    int nch = FD / KC;
    #pragma unroll
    for (int p = 0; p < SSTG - 1; p++)
        if (p < nch) issue(p);

    for (int ch = 0; ch < nch; ch++) {
        asm volatile("cp.async.wait_group %0;" :: "n"(SSTG - 2));
        __syncthreads();
        if (ch + SSTG - 1 < nch) issue(ch + SSTG - 1);
        else asm volatile("cp.async.commit_group;");

        float* as = sm + (ch % SSTG) * STAGE_F;
        float* bs = as + A_TILE_F;
        #pragma unroll
        for (int kk = 0; kk < 4; kk++) {
            int kof = kk * 8;
            uint32_t af[2][4];
            uint32_t bf[4][2];
            #pragma unroll
            for (int mt = 0; mt < 2; mt++) {
                int r0 = warpM + mt * 16 + (lane >> 2);
                int kc = kof + (lane & 3);
                af[mt][0] = cvt_rna(as[r0 * APAD + kc]);
                af[mt][1] = cvt_rna(as[(r0 + 8) * APAD + kc]);
                af[mt][2] = cvt_rna(as[r0 * APAD + kc + 4]);
                af[mt][3] = cvt_rna(as[(r0 + 8) * APAD + kc + 4]);
            }
            #pragma unroll
            for (int nt = 0; nt < 4; nt++) {
                int nc = warpN + nt * 8 + (lane >> 2);
                int kr = kof + (lane & 3);
                bf[nt][0] = __float_as_uint(bs[kr * BPAD + nc]);
                bf[nt][1] = __float_as_uint(bs[(kr + 4) * BPAD + nc]);
            }
            #pragma unroll
            for (int mt = 0; mt < 2; mt++)
                #pragma unroll
                for (int nt = 0; nt < 4; nt++)
                    mma8(acc[mt][nt], af[mt], bf[nt]);
        }
    }

    #pragma unroll
    for (int mt = 0; mt < 2; mt++) {
        #pragma unroll
        for (int nt = 0; nt < 4; nt++) {
            int r0 = grow + warpM + mt * 16 + (lane >> 2);
            int n0 = warpN + nt * 8 + 2 * (lane & 3);
            #pragma unroll
            for (int i = 0; i < 4; i++) {
                int r = r0 + ((i >= 2) ? 8 : 0);
                int n = n0 + (i & 1);
                float v = acc[mt][nt][i];
                v += bias[n];
                v = (v > 0.f) ? v : 0.01f * v;
                v *= g_dis[r];
                int b = r >> 11, m = r & (NN - 1);
                g_HhA[((size_t)b * FD + n) * NN + m] = __float2half_rn(v);
            }
        }
    }
}

// ---------------- fused big GEMM: 256 threads, warp 32x64, dbuf fragments ----------------
// Z = (dis*adj)@H (+X1 if layer==1). layer<2: H_next = fp16(dis*lrelu(Z@W+b)) fused.
#define KCB 64
#define BSTG 4
#define ATILE_BY 16384                     // 128 rows x 128B
#define STAGE 32768                        // A + B
#define WT_OFF (BSTG * STAGE)              // 131072, W^T 32KB
#define ZT_OFF 0                           // Z reuses stage 0/1 region post-mainloop
#define HT_OFF 65536                       // Ht reuses stage 2 region
#define HT_PITCH 272
#define BIG_SMEM (WT_OFF + 32768)          // 163840 <= 232448

__global__ __launch_bounds__(256, 1) void k_big(
    const float* __restrict__ bias_next, float* __restrict__ outext, int layer)
{
    extern __shared__ char smc[];
    uint32_t smb = (uint32_t)__cvta_generic_to_shared(smc);
    int tid = threadIdx.x, lane = tid & 31, warp = tid >> 5;
    int warpM = (warp & 3) * 32, warpN = (warp >> 2) * 64;
    int mtile = blockIdx.x, b = blockIdx.y;
    int mloc = mtile * 128;
    int grow = b * NN + mloc;

    const __half* Ah = g_Ah + (size_t)grow * NN;
    const __half* Bh = (layer == 1 ? g_HhB : g_HhA) + (size_t)b * FD * NN;
    __half* Hout = (layer == 0) ? g_HhB : g_HhA;

    float acc[2][8][4];
    #pragma unroll
    for (int mt = 0; mt < 2; mt++)
        #pragma unroll
        for (int nt = 0; nt < 8; nt++)
            #pragma unroll
            for (int i = 0; i < 4; i++) acc[mt][nt][i] = 0.f;

    // W^T preload (fp16 [fo][fi], two 64-fi 16KB k-blocks, SW128) -- oldest group
    if (layer < 2) {
        const __half* Wg = g_Wh[layer];
        #pragma unroll
        for (int j = 0; j < 8; j++) {
            int i = tid + 256 * j;
            int blk = i >> 10;
            int r = (i >> 3) & 127, c = i & 7;
            cp16(smb + WT_OFF + blk * 16384 + SWZ128((uint32_t)(r * 128 + c * 16)),
                 Wg + (size_t)r * FD + blk * 64 + c * 8);
        }
        asm volatile("cp.async.commit_group;");
    }

    auto issue = [&](int ch) {
        uint32_t base = smb + (ch & (BSTG - 1)) * STAGE;
        int kb = ch * KCB;
        #pragma unroll
        for (int j = 0; j < 4; j++) {              // 1024 16B segs per operand
            int i = tid + 256 * j;
            int r = i >> 3, c = i & 7;
            uint32_t dsw = SWZ128((uint32_t)(r * 128 + c * 16));
            size_t so = (size_t)r * NN + kb + c * 8;
            cp16(base + dsw,            Ah + so);
            cp16(base + ATILE_BY + dsw, Bh + so);
        }
        asm volatile("cp.async.commit_group;");
    };

    const int nch = NN / KCB;                      // 32
    issue(0); issue(1); issue(2);

    int mat = lane >> 3;
    // fragment double buffers
    uint32_t ah[2][2][4];
    uint32_t bf[2][8][2];

    auto loadA = [&](uint32_t base, int s, int buf) {
        #pragma unroll
        for (int mt = 0; mt < 2; mt++) {
            int row = warpM + mt * 16 + ((mat & 1) << 3) + (lane & 7);
            uint32_t col = (uint32_t)(s * 32 + ((mat >> 1) << 4));
            LDSM4(ah[buf][mt], base + SWZ128((uint32_t)(row * 128) + col));
        }
    };
    auto loadB = [&](uint32_t base, int s, int buf) {
        #pragma unroll
        for (int p = 0; p < 4; p++) {
            int nrow = warpN + (p * 2 + (mat >> 1)) * 8 + (lane & 7);
            uint32_t col = (uint32_t)(s * 32 + ((mat & 1) << 4));
            uint32_t t[4];
            LDSM4(t, base + ATILE_BY + SWZ128((uint32_t)(nrow * 128) + col));
            bf[buf][2 * p][0] = t[0]; bf[buf][2 * p][1] = t[1];
            bf[buf][2 * p + 1][0] = t[2]; bf[buf][2 * p + 1][1] = t[3];
        }
    };

    for (int ch = 0; ch < nch; ch++) {
        asm volatile("cp.async.wait_group 2;");
        __syncthreads();
        if (ch + 3 < nch) issue(ch + 3);
        else asm volatile("cp.async.commit_group;");

        uint32_t base = smb + (ch & (BSTG - 1)) * STAGE;
        loadA(base, 0, 0);
        loadB(base, 0, 0);
        #pragma unroll
        for (int s = 0; s < 4; s++) {              // four K=16 steps, dbuf'd
            int cur = s & 1;
            if (s < 3) {                           // prefetch next step's fragments
                loadA(base, s + 1, cur ^ 1);
                loadB(base, s + 1, cur ^ 1);
            }
            #pragma unroll
            for (int mt = 0; mt < 2; mt++)
                #pragma unroll
                for (int nt = 0; nt < 8; nt++)
                    mma_f16(acc[mt][nt], ah[cur][mt], bf[cur][nt]);
        }
    }

    if (layer == 2) {
        #pragma unroll
        for (int mt = 0; mt < 2; mt++)
            #pragma unroll
            for (int nt = 0; nt < 8; nt++) {
                int r0 = grow + warpM + mt * 16 + (lane >> 2);
                int n = warpN + nt * 8 + 2 * (lane & 3);
                #pragma unroll
                for (int h = 0; h < 2; h++) {
                    int r = r0 + h * 8;
                    float2 v = {acc[mt][nt][h * 2], acc[mt][nt][h * 2 + 1]};
                    *(float2*)(outext + (size_t)r * FD + n) = v;
                }
            }
        return;
    }

    // --- fused epilogue: Z -> stage 0/1 smem fp16 (two 16KB f-blocks), small GEMM, H_next ---
    // All warps are past the final barrier; stages 0-2 are no longer read.
    #pragma unroll
    for (int mt = 0; mt < 2; mt++)
        #pragma unroll
        for (int nt = 0; nt < 8; nt++) {
            int rl0 = warpM + mt * 16 + (lane >> 2);
            int f = warpN + nt * 8 + 2 * (lane & 3);
            #pragma unroll
            for (int h = 0; h < 2; h++) {
                int rl = rl0 + h * 8;
                float zx = acc[mt][nt][h * 2], zy = acc[mt][nt][h * 2 + 1];
                if (layer == 1) {
                    __half2 rv = *(const __half2*)(g_Xh1 + (size_t)(grow + rl) * FD + f);
                    float2 rf = __half22float2(rv);
                    zx += rf.x; zy += rf.y;
                }
                __half2 hz = __floats2half2_rn(zx, zy);
                uint32_t zo = ZT_OFF + (uint32_t)((f >> 6) << 14)
                            + SWZ128((uint32_t)(rl * 128 + (f & 63) * 2));
                *(__half2*)(smc + zo) = hz;
                if (layer == 0)
                    *(__half2*)(g_Xh1 + (size_t)(grow + rl) * FD + f) = hz;
            }
        }
    asm volatile("cp.async.wait_group 0;");        // W resident
    __syncthreads();

    #pragma unroll
    for (int mt = 0; mt < 2; mt++)
        #pragma unroll
        for (int nt = 0; nt < 8; nt++)
            #pragma unroll
            for (int i = 0; i < 4; i++) acc[mt][nt][i] = 0.f;

    #pragma unroll
    for (int wz = 0; wz < 2; wz++) {               // two 64-fi K-blocks
        uint32_t za = smb + ZT_OFF + wz * 16384;
        uint32_t wa = smb + WT_OFF + wz * 16384;
        loadA(za - 0, 0, 0);                       // reuse helpers on Z/W tiles:
        // NOTE: loadA/loadB assume base layout (A at +0, B at +ATILE_BY); for the
        // small GEMM the W tile is at a different offset, so load explicitly:
        #pragma unroll
        for (int s = 0; s < 4; s++) {
            uint32_t ahs[2][4];
            #pragma unroll
            for (int mt = 0; mt < 2; mt++) {
                int row = warpM + mt * 16 + ((mat & 1) << 3) + (lane & 7);
                uint32_t col = (uint32_t)(s * 32 + ((mat >> 1) << 4));
                LDSM4(ahs[mt], za + SWZ128((uint32_t)(row * 128) + col));
            }
            uint32_t bfs[8][2];
            #pragma unroll
            for (int p = 0; p < 4; p++) {
                int nrow = warpN + (p * 2 + (mat >> 1)) * 8 + (lane & 7);
                uint32_t col = (uint32_t)(s * 32 + ((mat & 1) << 4));
                uint32_t t[4];
                LDSM4(t, wa + SWZ128((uint32_t)(nrow * 128) + col));
                bfs[2 * p][0] = t[0]; bfs[2 * p][1] = t[1];
                bfs[2 * p + 1][0] = t[2]; bfs[2 * p + 1][1] = t[3];
            }
            #pragma unroll
            for (int mt = 0; mt < 2; mt++)
                #pragma unroll
                for (int nt = 0; nt < 8; nt++)
                    mma_f16(acc[mt][nt], ahs[mt], bfs[nt]);
        }
    }
    __syncthreads();                               // Z reads done; reuse HT region

    // epilogue2: H = fp16(dis*lrelu(acc+bias)) -> Ht smem [f][m] at HT_OFF
    #pragma unroll
    for (int mt = 0; mt < 2; mt++)
        #pragma unroll
        for (int nt = 0; nt < 8; nt++) {
            int rl0 = warpM + mt * 16 + (lane >> 2);
            int f = warpN + nt * 8 + 2 * (lane & 3);
            float bx = bias_next[f], by = bias_next[f + 1];
            #pragma unroll
            for (int h = 0; h < 2; h++) {
                int rl = rl0 + h * 8;
                float d = g_dis[grow + rl];
                float vx = acc[mt][nt][h * 2] + bx;
                float vy = acc[mt][nt][h * 2 + 1] + by;
                vx = (vx > 0.f) ? vx : 0.01f * vx;
                vy = (vy > 0.f) ? vy : 0.01f * vy;
                *(__half*)(smc + HT_OFF + f * HT_PITCH + rl * 2) = __float2half_rn(vx * d);
                *(__half*)(smc + HT_OFF + (f + 1) * HT_PITCH + rl * 2) = __float2half_rn(vy * d);
            }
        }
    __syncthreads();

    {   // coalesced write: 128 f-rows x 128 m x 2B
        int f = tid >> 1, seg = tid & 1;
        const char* src = smc + HT_OFF + f * HT_PITCH + seg * 128;
        __half* dst = Hout + ((size_t)b * FD + f) * NN + mloc + seg * 64;
        #pragma unroll
        for (int j = 0; j < 8; j++)
            *(float4*)(dst + j * 8) = *(const float4*)(src + j * 16);
    }
}

// ---------------- launch ----------------
extern "C" void kernel_launch(void* const* d_in, const int* in_sizes, int n_in,
                              void* d_out, int out_size) {
    (void)in_sizes; (void)n_in; (void)out_size;
    const float* X   = (const float*)d_in[0];
    const float* adj = (const float*)d_in[1];
    const float* W1  = (const float*)d_in[2];
    const float* b1  = (const float*)d_in[3];
    const float* W2  = (const float*)d_in[4];
    const float* b2  = (const float*)d_in[5];
    const float* W3  = (const float*)d_in[6];
    const float* b3  = (const float*)d_in[7];
    float* out = (float*)d_out;

    cudaFuncSetAttribute(k_small, cudaFuncAttributeMaxDynamicSharedMemorySize, SMALL_SMEM);
    cudaFuncSetAttribute(k_big,   cudaFuncAttributeMaxDynamicSharedMemorySize, BIG_SMEM);

    k_prep<<<NB * NN, 256>>>(adj);
    k_prepW<<<(3 * FD * FD) / 256, 256>>>(W1, W2, W3);

    k_small<<<16384 / 128, NT, SMALL_SMEM>>>(X, b1);           // H1 -> g_HhA
    k_big<<<dim3(16, NB), 256, BIG_SMEM>>>(b2, out, 0);        // Z1, H2 -> g_HhB, X1
    k_big<<<dim3(16, NB), 256, BIG_SMEM>>>(b3, out, 1);        // Z2(+X1), H3 -> g_HhA
    k_big<<<dim3(16, NB), 256, BIG_SMEM>>>(b1, out, 2);        // out = A'@H3
}